// round 9
// baseline (speedup 1.0000x reference)
#include <cuda_runtime.h>

#define EPS 1e-6f

// x: (2048, 4096, 16) fp32  -> 8,388,608 rows of 16 floats (64 B each)
// Grade slices over last dim: [0,1) [1,5) [5,11) [11,15) [15,16)
// out[..., a:b] = x[..., a:b] * rsqrt(sum(x[a:b]^2) + eps) * scale[g]
//
// CONVERGED HBM-streaming kernel: 6.8 TB/s (86% of spec), the measured
// ceiling for a 1:1 R/W interleaved stream on GB300. The decisive lever
// was sm_103a 256-bit global ld/st (2x ld.global.nc.v8.f32 +
// 2x st.global.v8.f32 per 64B row), halving LSU wavefronts vs 128-bit.
// One-shot launch, 1 row/thread: block-level concurrency saturates the
// LTS queues; cache hints / more MLP / persistent loops all measured
// neutral-or-worse (R3, R5, R6, R7).

__device__ __forceinline__ void ld256(const float* __restrict__ p, float* r)
{
    asm volatile("ld.global.nc.v8.f32 {%0,%1,%2,%3,%4,%5,%6,%7}, [%8];"
                 : "=f"(r[0]), "=f"(r[1]), "=f"(r[2]), "=f"(r[3]),
                   "=f"(r[4]), "=f"(r[5]), "=f"(r[6]), "=f"(r[7])
                 : "l"(p));
}

__device__ __forceinline__ void st256(float* __restrict__ p, const float* r)
{
    asm volatile("st.global.v8.f32 [%0], {%1,%2,%3,%4,%5,%6,%7,%8};"
                 :: "l"(p),
                    "f"(r[0]), "f"(r[1]), "f"(r[2]), "f"(r[3]),
                    "f"(r[4]), "f"(r[5]), "f"(r[6]), "f"(r[7])
                 : "memory");
}

__global__ void __launch_bounds__(256)
gradewise_ln_kernel(const float* __restrict__ x,
                    const float* __restrict__ scale,
                    float*       __restrict__ out,
                    int nrows)
{
    int row = blockIdx.x * blockDim.x + threadIdx.x;
    if (row >= nrows) return;

    size_t base = (size_t)row * 16;

    float v[16];
    ld256(x + base,     v);
    ld256(x + base + 8, v + 8);

    // grade sums of squares over slices [0,1) [1,5) [5,11) [11,15) [15,16)
    float s0 = v[0] * v[0];
    float s1 = v[1] * v[1] + v[2] * v[2] + v[3] * v[3] + v[4] * v[4];
    float s2 = v[5] * v[5] + v[6] * v[6] + v[7] * v[7]
             + v[8] * v[8] + v[9] * v[9] + v[10] * v[10];
    float s3 = v[11] * v[11] + v[12] * v[12] + v[13] * v[13] + v[14] * v[14];
    float s4 = v[15] * v[15];

    float r0 = rsqrtf(s0 + EPS) * __ldg(&scale[0]);
    float r1 = rsqrtf(s1 + EPS) * __ldg(&scale[1]);
    float r2 = rsqrtf(s2 + EPS) * __ldg(&scale[2]);
    float r3 = rsqrtf(s3 + EPS) * __ldg(&scale[3]);
    float r4 = rsqrtf(s4 + EPS) * __ldg(&scale[4]);

    float o[16];
    o[0]  = v[0]  * r0;
    o[1]  = v[1]  * r1;  o[2]  = v[2]  * r1;  o[3]  = v[3]  * r1;
    o[4]  = v[4]  * r1;
    o[5]  = v[5]  * r2;  o[6]  = v[6]  * r2;  o[7]  = v[7]  * r2;
    o[8]  = v[8]  * r2;  o[9]  = v[9]  * r2;  o[10] = v[10] * r2;
    o[11] = v[11] * r3;  o[12] = v[12] * r3;  o[13] = v[13] * r3;
    o[14] = v[14] * r3;
    o[15] = v[15] * r4;

    st256(out + base,     o);
    st256(out + base + 8, o + 8);
}

extern "C" void kernel_launch(void* const* d_in, const int* in_sizes, int n_in,
                              void* d_out, int out_size)
{
    const float* x     = (const float*)d_in[0];
    const float* scale = (const float*)d_in[1];
    float*       out   = (float*)d_out;

    int nrows = in_sizes[0] / 16;  // 2048*4096 = 8,388,608

    const int threads = 256;
    int blocks = (nrows + threads - 1) / threads;

    gradewise_ln_kernel<<<blocks, threads>>>(x, scale, out, nrows);
}

// round 10
// speedup vs baseline: 1.0014x; 1.0014x over previous
#include <cuda_runtime.h>

#define EPS 1e-6f

// x: (2048, 4096, 16) fp32  -> 8,388,608 rows of 16 floats (64 B each)
// Grade slices over last dim: [0,1) [1,5) [5,11) [11,15) [15,16)
// out[..., a:b] = x[..., a:b] * rsqrt(sum(x[a:b]^2) + eps) * scale[g]
//
// HBM-streaming kernel. Loads/stores are layout-decoupled from rows:
// thread t handles the contiguous 32B at chunk_base + t*32 (a HALF-row),
// so every warp-level v8 instruction covers 1024B fully contiguous
// (8 lines/instr instead of 16 strided). Grade 2 spans the half boundary;
// the two lanes of a row (t, t^1) exchange s2 partials via one shfl.
// Two chunks/thread, front-batched loads; grid identical to the R4 anchor.

__device__ __forceinline__ void ld256(const float* __restrict__ p, float* r)
{
    asm volatile("ld.global.nc.v8.f32 {%0,%1,%2,%3,%4,%5,%6,%7}, [%8];"
                 : "=f"(r[0]), "=f"(r[1]), "=f"(r[2]), "=f"(r[3]),
                   "=f"(r[4]), "=f"(r[5]), "=f"(r[6]), "=f"(r[7])
                 : "l"(p));
}

__device__ __forceinline__ void st256(float* __restrict__ p, const float* r)
{
    asm volatile("st.global.v8.f32 [%0], {%1,%2,%3,%4,%5,%6,%7,%8};"
                 :: "l"(p),
                    "f"(r[0]), "f"(r[1]), "f"(r[2]), "f"(r[3]),
                    "f"(r[4]), "f"(r[5]), "f"(r[6]), "f"(r[7])
                 : "memory");
}

// Process one half-row held in v[8]. odd==0: elements 0..7 of the row
// (grades 0, 1, and the low part of 2). odd==1: elements 8..15
// (high part of grade 2, grades 3, 4).
__device__ __forceinline__ void half_row(const float* __restrict__ v,
                                         float* __restrict__ o,
                                         bool odd,
                                         float sc0, float sc1, float sc2,
                                         float sc3, float sc4)
{
    float q0 = v[0] * v[0], q1 = v[1] * v[1], q2 = v[2] * v[2],
          q3 = v[3] * v[3], q4 = v[4] * v[4], q5 = v[5] * v[5],
          q6 = v[6] * v[6], q7 = v[7] * v[7];

    // grade-2 partial: even lane owns row elems 5,6,7 -> q5+q6+q7
    //                  odd  lane owns row elems 8,9,10 -> q0+q1+q2
    float s2p = odd ? (q0 + q1 + q2) : (q5 + q6 + q7);
    float s2  = s2p + __shfl_xor_sync(0xffffffffu, s2p, 1);
    float r2  = rsqrtf(s2 + EPS) * sc2;

    if (!odd) {
        float r0 = rsqrtf(q0 + EPS) * sc0;
        float r1 = rsqrtf(q1 + q2 + q3 + q4 + EPS) * sc1;
        o[0] = v[0] * r0;
        o[1] = v[1] * r1; o[2] = v[2] * r1; o[3] = v[3] * r1; o[4] = v[4] * r1;
        o[5] = v[5] * r2; o[6] = v[6] * r2; o[7] = v[7] * r2;
    } else {
        float r3 = rsqrtf(q3 + q4 + q5 + q6 + EPS) * sc3;
        float r4 = rsqrtf(q7 + EPS) * sc4;
        o[0] = v[0] * r2; o[1] = v[1] * r2; o[2] = v[2] * r2;
        o[3] = v[3] * r3; o[4] = v[4] * r3; o[5] = v[5] * r3; o[6] = v[6] * r3;
        o[7] = v[7] * r4;
    }
}

__global__ void __launch_bounds__(256)
gradewise_ln_kernel(const float* __restrict__ x,
                    const float* __restrict__ scale,
                    float*       __restrict__ out,
                    int nhalves)   // total half-rows = nrows*2 (multiple of 512)
{
    int t = threadIdx.x;
    bool odd = t & 1;

    // Block covers 512 consecutive half-rows (= 256 rows = 16 KB):
    // chunk0 = halves [blk*512 + t], chunk1 = halves [blk*512 + 256 + t].
    int h0 = blockIdx.x * 512 + t;
    int h1 = h0 + 256;
    if (h1 >= nhalves) {           // exact division in practice; safe tail
        if (h0 < nhalves) {
            size_t b0 = (size_t)h0 * 8;
            float v[8], o[8];
            ld256(x + b0, v);
            float sc0 = __ldg(&scale[0]), sc1 = __ldg(&scale[1]),
                  sc2 = __ldg(&scale[2]), sc3 = __ldg(&scale[3]),
                  sc4 = __ldg(&scale[4]);
            half_row(v, o, odd, sc0, sc1, sc2, sc3, sc4);
            st256(out + b0, o);
        }
        return;
    }

    size_t b0 = (size_t)h0 * 8;
    size_t b1 = (size_t)h1 * 8;

    // Front-batch both 256-bit loads (2 independent LDGs in flight).
    float va[8], vb[8];
    ld256(x + b0, va);
    ld256(x + b1, vb);

    float sc0 = __ldg(&scale[0]);
    float sc1 = __ldg(&scale[1]);
    float sc2 = __ldg(&scale[2]);
    float sc3 = __ldg(&scale[3]);
    float sc4 = __ldg(&scale[4]);

    float oa[8], ob[8];
    half_row(va, oa, odd, sc0, sc1, sc2, sc3, sc4);
    half_row(vb, ob, odd, sc0, sc1, sc2, sc3, sc4);

    st256(out + b0, oa);
    st256(out + b1, ob);
}

extern "C" void kernel_launch(void* const* d_in, const int* in_sizes, int n_in,
                              void* d_out, int out_size)
{
    const float* x     = (const float*)d_in[0];
    const float* scale = (const float*)d_in[1];
    float*       out   = (float*)d_out;

    int nhalves = in_sizes[0] / 8;   // 16,777,216 half-rows

    const int threads = 256;
    const int halves_per_block = threads * 2;  // 512
    int blocks = (nhalves + halves_per_block - 1) / halves_per_block;  // 32768

    gradewise_ln_kernel<<<blocks, threads>>>(x, scale, out, nhalves);
}

// round 11
// speedup vs baseline: 1.0029x; 1.0014x over previous
#include <cuda_runtime.h>

#define EPS 1e-6f

// x: (2048, 4096, 16) fp32  -> 8,388,608 rows of 16 floats (64 B each)
// Grade slices over last dim: [0,1) [1,5) [5,11) [11,15) [15,16)
// out[..., a:b] = x[..., a:b] * rsqrt(sum(x[a:b]^2) + eps) * scale[g]
//
// CONVERGED HBM-streaming kernel: ~6.8 TB/s (85-86% of 8 TB/s spec), the
// measured GB300 ceiling for a 1:1 R/W interleaved stream. Decisive lever:
// sm_103a 256-bit global ld/st (2x ld.global.nc.v8.f32 +
// 2x st.global.v8.f32 per 64B row), halving LSU wavefronts vs 128-bit
// (R4: 166->157us, DRAM 77->86%). All other axes measured neutral/worse:
// cache hints (R3, R7), deeper MLP / persistent grid (R3, R5, R6),
// occupancy 57-89% (R9), contiguous-vs-strided warp layout (R9).

__device__ __forceinline__ void ld256(const float* __restrict__ p, float* r)
{
    asm volatile("ld.global.nc.v8.f32 {%0,%1,%2,%3,%4,%5,%6,%7}, [%8];"
                 : "=f"(r[0]), "=f"(r[1]), "=f"(r[2]), "=f"(r[3]),
                   "=f"(r[4]), "=f"(r[5]), "=f"(r[6]), "=f"(r[7])
                 : "l"(p));
}

__device__ __forceinline__ void st256(float* __restrict__ p, const float* r)
{
    asm volatile("st.global.v8.f32 [%0], {%1,%2,%3,%4,%5,%6,%7,%8};"
                 :: "l"(p),
                    "f"(r[0]), "f"(r[1]), "f"(r[2]), "f"(r[3]),
                    "f"(r[4]), "f"(r[5]), "f"(r[6]), "f"(r[7])
                 : "memory");
}

__global__ void __launch_bounds__(256)
gradewise_ln_kernel(const float* __restrict__ x,
                    const float* __restrict__ scale,
                    float*       __restrict__ out,
                    int nrows)
{
    int row = blockIdx.x * blockDim.x + threadIdx.x;
    if (row >= nrows) return;

    size_t base = (size_t)row * 16;

    float v[16];
    ld256(x + base,     v);
    ld256(x + base + 8, v + 8);

    // grade sums of squares over slices [0,1) [1,5) [5,11) [11,15) [15,16)
    float s0 = v[0] * v[0];
    float s1 = v[1] * v[1] + v[2] * v[2] + v[3] * v[3] + v[4] * v[4];
    float s2 = v[5] * v[5] + v[6] * v[6] + v[7] * v[7]
             + v[8] * v[8] + v[9] * v[9] + v[10] * v[10];
    float s3 = v[11] * v[11] + v[12] * v[12] + v[13] * v[13] + v[14] * v[14];
    float s4 = v[15] * v[15];

    float r0 = rsqrtf(s0 + EPS) * __ldg(&scale[0]);
    float r1 = rsqrtf(s1 + EPS) * __ldg(&scale[1]);
    float r2 = rsqrtf(s2 + EPS) * __ldg(&scale[2]);
    float r3 = rsqrtf(s3 + EPS) * __ldg(&scale[3]);
    float r4 = rsqrtf(s4 + EPS) * __ldg(&scale[4]);

    float o[16];
    o[0]  = v[0]  * r0;
    o[1]  = v[1]  * r1;  o[2]  = v[2]  * r1;  o[3]  = v[3]  * r1;
    o[4]  = v[4]  * r1;
    o[5]  = v[5]  * r2;  o[6]  = v[6]  * r2;  o[7]  = v[7]  * r2;
    o[8]  = v[8]  * r2;  o[9]  = v[9]  * r2;  o[10] = v[10] * r2;
    o[11] = v[11] * r3;  o[12] = v[12] * r3;  o[13] = v[13] * r3;
    o[14] = v[14] * r3;
    o[15] = v[15] * r4;

    st256(out + base,     o);
    st256(out + base + 8, o + 8);
}

extern "C" void kernel_launch(void* const* d_in, const int* in_sizes, int n_in,
                              void* d_out, int out_size)
{
    const float* x     = (const float*)d_in[0];
    const float* scale = (const float*)d_in[1];
    float*       out   = (float*)d_out;

    int nrows = in_sizes[0] / 16;  // 2048*4096 = 8,388,608

    const int threads = 256;
    int blocks = (nrows + threads - 1) / threads;

    gradewise_ln_kernel<<<blocks, threads>>>(x, scale, out, nrows);
}